// round 13
// baseline (speedup 1.0000x reference)
#include <cuda_runtime.h>
#include <cuda_bf16.h>
#include <cstdint>

#define CO   256
#define CI   2048
#define HW   1024
#define NB   8

__device__ unsigned int   g_amax;
__device__ __nv_bfloat16  g_wq[CO * CI];
__device__ float          g_scale[CO];
__device__ float          g_bq[CO];

__device__ __forceinline__ uint32_t smem_u32(const void* p) {
    return static_cast<uint32_t>(__cvta_generic_to_shared(p));
}

__global__ void init_kernel() { g_amax = 0u; }

__global__ void amax_kernel(const float* __restrict__ x, int n4) {
    const float4* x4 = reinterpret_cast<const float4*>(x);
    float m = 0.f;
    for (int i = blockIdx.x * blockDim.x + threadIdx.x; i < n4; i += gridDim.x * blockDim.x) {
        float4 v = x4[i];
        m = fmaxf(m, fmaxf(fmaxf(fabsf(v.x), fabsf(v.y)), fmaxf(fabsf(v.z), fabsf(v.w))));
    }
    #pragma unroll
    for (int o = 16; o; o >>= 1) m = fmaxf(m, __shfl_xor_sync(0xffffffffu, m, o));
    __shared__ float red[8];
    if ((threadIdx.x & 31) == 0) red[threadIdx.x >> 5] = m;
    __syncthreads();
    if (threadIdx.x < 8) {
        m = red[threadIdx.x];
        #pragma unroll
        for (int o = 4; o; o >>= 1) m = fmaxf(m, __shfl_xor_sync(0xffu, m, o));
        if (threadIdx.x == 0) atomicMax(&g_amax, __float_as_uint(m));
    }
}

__global__ void wprep_kernel(const float* __restrict__ w, const float* __restrict__ bias) {
    const int co  = blockIdx.x;
    const int tid = threadIdx.x;
    const float* wr = w + (size_t)co * CI;
    float vals[8];
    float m = 0.f;
    #pragma unroll
    for (int j = 0; j < 8; j++) {
        vals[j] = wr[tid + 256 * j];
        m = fmaxf(m, fabsf(vals[j]));
    }
    #pragma unroll
    for (int o = 16; o; o >>= 1) m = fmaxf(m, __shfl_xor_sync(0xffffffffu, m, o));
    __shared__ float red[8];
    __shared__ float s_sw_sh;
    if ((tid & 31) == 0) red[tid >> 5] = m;
    __syncthreads();
    if (tid == 0) {
        float mm = red[0];
        #pragma unroll
        for (int i = 1; i < 8; i++) mm = fmaxf(mm, red[i]);
        float s_w = fmaxf(mm, 1e-8f) / 127.f;
        s_sw_sh = s_w;
        float s_a = fmaxf(__uint_as_float(g_amax), 1e-8f) / 127.f;
        float s_b = s_a * s_w;
        g_scale[co] = s_b;
        g_bq[co]    = rintf(bias[co] / s_b) * s_b;
    }
    __syncthreads();
    const float s_w = s_sw_sh;
    #pragma unroll
    for (int j = 0; j < 8; j++) {
        float q = fminf(fmaxf(rintf(vals[j] / s_w), -128.f), 127.f);
        g_wq[(size_t)co * CI + tid + 256 * j] = __float2bfloat16(q);
    }
}

// ---- GEMM: BM=128, BN=128, BK=32; 8 mma warps (64x32) + 4 producer warps; 4-stage ring ----
#define BM   128
#define BN   128
#define BK   32
#define NST  4
#define KT_N (CI / BK)       // 64

#define AROWB 80             // A smem row stride bytes
#define BROWB 272            // B smem row stride bytes (256 data + 16 pad)
#define A_ST  (BM * AROWB)   // 10240
#define B_ST  (BK * BROWB)   // 8704
#define OFF_FULL  0
#define OFF_EMPTY 32
#define OFF_A     128
#define OFF_B     (OFF_A + NST * A_ST)
#define SMEM_BYTES (OFF_B + NST * B_ST)   // 76032

__device__ __forceinline__ void mbar_init(uint32_t mbar, uint32_t cnt) {
    asm volatile("mbarrier.init.shared.b64 [%0], %1;" :: "r"(mbar), "r"(cnt) : "memory");
}
__device__ __forceinline__ void mbar_arrive(uint32_t mbar) {
    asm volatile("mbarrier.arrive.shared.b64 _, [%0];" :: "r"(mbar) : "memory");
}
__device__ __forceinline__ void mbar_wait(uint32_t mbar, uint32_t parity) {
    asm volatile(
        "{\n\t.reg .pred P;\n"
        "W%=:\n\t"
        "mbarrier.try_wait.parity.acquire.cta.shared::cta.b64 P, [%0], %1, 0x989680;\n\t"
        "@P bra D%=;\n\t"
        "bra W%=;\n"
        "D%=:\n\t}"
        :: "r"(mbar), "r"(parity) : "memory");
}

__global__ __launch_bounds__(384, 1) void gemm_kernel(const float* __restrict__ x,
                                                      float* __restrict__ out) {
    extern __shared__ __align__(16) char smem[];
    const uint32_t sb = smem_u32(smem);
    const uint32_t sA = sb + OFF_A;
    const uint32_t sB = sb + OFF_B;

    const int tid  = threadIdx.x;
    const int lane = tid & 31;
    const int warp = tid >> 5;

    const int tileM = blockIdx.x;            // 0..1 (fastest -> L2 x reuse)
    const int tileN = blockIdx.y;            // 0..63
    const int b     = tileN >> 3;
    const int hw0   = (tileN & 7) * BN;
    const float* xb = x + (size_t)b * CI * HW + hw0;

    if (tid == 0) {
        #pragma unroll
        for (int i = 0; i < NST; i++) {
            mbar_init(sb + OFF_FULL  + 8 * i, 128);   // producer threads
            mbar_init(sb + OFF_EMPTY + 8 * i, 256);   // consumer threads
        }
    }
    __syncthreads();

    if (warp >= 8) {
        // ===================== PRODUCER (warps 8-11) =====================
        const int ptid  = tid - 256;           // 0..127
        const int xrow  = ptid >> 3;           // 0..15 (+16)
        const int hwseg = (ptid & 7) * 16;     // 0..112 (16 hw each)
        const int arow  = ptid;                // 0..127

        const float s_a    = fmaxf(__uint_as_float(g_amax), 1e-8f) / 127.f;
        const float inv_sa = 1.f / s_a;
        const float MAGIC  = 12582912.f;       // 1.5 * 2^23

        const __nv_bfloat16* wq = g_wq + (size_t)(tileM * BM) * CI;

        for (int s = 0; s < KT_N; s++) {
            const int slot = s & (NST - 1);
            const uint32_t ph = (((unsigned)s >> 2) & 1u) ^ 1u;
            mbar_wait(sb + OFF_EMPTY + 8 * slot, ph);

            // A: one 64B row per thread via cp.async
            {
                const __nv_bfloat16* src = wq + (size_t)arow * CI + s * BK;
                uint32_t dst = sA + slot * A_ST + arow * AROWB;
                #pragma unroll
                for (int j = 0; j < 4; j++)
                    asm volatile("cp.async.cg.shared.global [%0], [%1], 16;\n"
                                 :: "r"(dst + j * 16), "l"(src + j * 8));
                asm volatile("cp.async.commit_group;\n");
            }
            // B: two rows of 16 floats each -> quantize -> STS
            #pragma unroll
            for (int h = 0; h < 2; h++) {
                const int r = xrow + 16 * h;
                const float* src = xb + (size_t)(s * BK + r) * HW + hwseg;
                float4 v0 = *reinterpret_cast<const float4*>(src);
                float4 v1 = *reinterpret_cast<const float4*>(src + 4);
                float4 v2 = *reinterpret_cast<const float4*>(src + 8);
                float4 v3 = *reinterpret_cast<const float4*>(src + 12);
                uint32_t pk[8];
                float f[16] = { v0.x, v0.y, v0.z, v0.w, v1.x, v1.y, v1.z, v1.w,
                                v2.x, v2.y, v2.z, v2.w, v3.x, v3.y, v3.z, v3.w };
                #pragma unroll
                for (int j = 0; j < 8; j++) {
                    float q0 = fmaf(f[2 * j],     inv_sa, MAGIC) - MAGIC;
                    float q1 = fmaf(f[2 * j + 1], inv_sa, MAGIC) - MAGIC;
                    __nv_bfloat162 p = __floats2bfloat162_rn(q0, q1);
                    pk[j] = *reinterpret_cast<uint32_t*>(&p);
                }
                uint32_t dst = sB + slot * B_ST + r * BROWB + hwseg * 2;
                asm volatile("st.shared.v4.b32 [%0], {%1,%2,%3,%4};"
                             :: "r"(dst), "r"(pk[0]), "r"(pk[1]), "r"(pk[2]), "r"(pk[3]));
                asm volatile("st.shared.v4.b32 [%0], {%1,%2,%3,%4};"
                             :: "r"(dst + 16), "r"(pk[4]), "r"(pk[5]), "r"(pk[6]), "r"(pk[7]));
            }
            asm volatile("cp.async.wait_group 0;\n");
            mbar_arrive(sb + OFF_FULL + 8 * slot);
        }
        return;
    }

    // ===================== CONSUMER (warps 0-7): 64x32 tiles =====================
    const int wm = warp >> 2;   // 0..1 -> 64 co rows
    const int wn = warp & 3;    // 0..3 -> 32 hw cols

    float acc[4][4][4];
    #pragma unroll
    for (int mt = 0; mt < 4; mt++)
        #pragma unroll
        for (int nt = 0; nt < 4; nt++)
            #pragma unroll
            for (int r = 0; r < 4; r++) acc[mt][nt][r] = 0.f;

    const uint32_t aoff = (uint32_t)(wm * 64 + (lane & 15)) * AROWB + (lane >> 4) * 16;
    const uint32_t boff = (uint32_t)(lane & 15) * BROWB + wn * 64 + (lane >> 4) * 16;

    for (int s = 0; s < KT_N; s++) {
        const int slot = s & (NST - 1);
        const uint32_t ph = ((unsigned)s >> 2) & 1u;
        mbar_wait(sb + OFF_FULL + 8 * slot, ph);
        const uint32_t aS = sA + slot * A_ST;
        const uint32_t bS = sB + slot * B_ST;

        #pragma unroll
        for (int kk = 0; kk < 2; kk++) {
            uint32_t a[4][4];
            #pragma unroll
            for (int mt = 0; mt < 4; mt++) {
                uint32_t addr = aS + aoff + mt * 16 * AROWB + kk * 32;
                asm volatile("ldmatrix.sync.aligned.m8n8.x4.shared.b16 {%0,%1,%2,%3}, [%4];"
                             : "=r"(a[mt][0]), "=r"(a[mt][1]), "=r"(a[mt][2]), "=r"(a[mt][3])
                             : "r"(addr));
            }
            uint32_t bf[2][4];
            #pragma unroll
            for (int np = 0; np < 2; np++) {
                uint32_t addr = bS + boff + np * 32 + kk * 16 * BROWB;
                asm volatile("ldmatrix.sync.aligned.m8n8.x4.trans.shared.b16 {%0,%1,%2,%3}, [%4];"
                             : "=r"(bf[np][0]), "=r"(bf[np][1]), "=r"(bf[np][2]), "=r"(bf[np][3])
                             : "r"(addr));
            }
            #pragma unroll
            for (int mt = 0; mt < 4; mt++) {
                #pragma unroll
                for (int nt = 0; nt < 4; nt++) {
                    uint32_t b0 = bf[nt >> 1][(nt & 1) * 2 + 0];
                    uint32_t b1 = bf[nt >> 1][(nt & 1) * 2 + 1];
                    asm volatile(
                        "mma.sync.aligned.m16n8k16.row.col.f32.bf16.bf16.f32 "
                        "{%0,%1,%2,%3}, {%4,%5,%6,%7}, {%8,%9}, {%0,%1,%2,%3};"
                        : "+f"(acc[mt][nt][0]), "+f"(acc[mt][nt][1]),
                          "+f"(acc[mt][nt][2]), "+f"(acc[mt][nt][3])
                        : "r"(a[mt][0]), "r"(a[mt][1]), "r"(a[mt][2]), "r"(a[mt][3]),
                          "r"(b0), "r"(b1));
                }
            }
        }
        mbar_arrive(sb + OFF_EMPTY + 8 * slot);
    }

    // epilogue
    #pragma unroll
    for (int mt = 0; mt < 4; mt++) {
        int co0 = tileM * BM + wm * 64 + mt * 16 + (lane >> 2);
        float s0 = g_scale[co0],     q0 = g_bq[co0];
        float s1 = g_scale[co0 + 8], q1 = g_bq[co0 + 8];
        #pragma unroll
        for (int nt = 0; nt < 4; nt++) {
            int hw = hw0 + wn * 32 + nt * 8 + (lane & 3) * 2;
            float* o = out + (size_t)b * CO * HW + (size_t)co0 * HW + hw;
            float2 v0 = make_float2(acc[mt][nt][0] * s0 + q0, acc[mt][nt][1] * s0 + q0);
            float2 v1 = make_float2(acc[mt][nt][2] * s1 + q1, acc[mt][nt][3] * s1 + q1);
            *reinterpret_cast<float2*>(o) = v0;
            *reinterpret_cast<float2*>(o + 8 * HW) = v1;
        }
    }
}

extern "C" void kernel_launch(void* const* d_in, const int* in_sizes, int n_in,
                              void* d_out, int out_size) {
    const float* x    = (const float*)d_in[0];
    const float* w    = (const float*)d_in[1];
    const float* bias = (const float*)d_in[2];
    float* out        = (float*)d_out;

    cudaFuncSetAttribute(gemm_kernel, cudaFuncAttributeMaxDynamicSharedMemorySize, SMEM_BYTES);

    init_kernel<<<1, 1>>>();
    const int n4 = (NB * CI * HW) / 4;
    amax_kernel<<<1024, 256>>>(x, n4);
    wprep_kernel<<<CO, 256>>>(w, bias);
    dim3 grid(2, 64);
    gemm_kernel<<<grid, 384, SMEM_BYTES>>>(x, out);
}